// round 10
// baseline (speedup 1.0000x reference)
#include <cuda_runtime.h>
#include <math.h>
#include <stdint.h>

#define BB 256
#define DD 4096
#define TT 19
#define CAP 384

// ---------------- static device scratch ------------------------------------
__device__ float g_grad[BB * DD];                     // 4 MB  grad_x = xW + b
__device__ signed char g_As8[BB * DD];                // 1 MB  x as s8
__device__ signed char g_Bq[3][(size_t)DD * DD];      // 48 MB W digit planes
__device__ int2 g_cand[(size_t)BB * TT * CAP];        // 15 MB candidate lists
__device__ int  g_cnt[BB * TT];
__device__ float g_lmax[BB];

// ---------------------------------------------------------------------------
// conv_w: W fp32 -> 3 balanced s8 digit planes of rint(W * 2^26).
// ---------------------------------------------------------------------------
union B8 { signed char c[8]; uint2 u; };

__global__ void __launch_bounds__(256) conv_w(const float* __restrict__ W)
{
    size_t e = ((size_t)blockIdx.x * 256 + threadIdx.x) * 8;
    float4 a = *reinterpret_cast<const float4*>(W + e);
    float4 b = *reinterpret_cast<const float4*>(W + e + 4);
    float w[8] = {a.x, a.y, a.z, a.w, b.x, b.y, b.z, b.w};
    B8 p0, p1, p2;
#pragma unroll
    for (int i = 0; i < 8; i++) {
        int v = __float2int_rn(w[i] * 67108864.0f);
        v = max(-8000000, min(8000000, v));
        int d0 = ((v + 128) & 255) - 128; v = (v - d0) >> 8;
        int d1 = ((v + 128) & 255) - 128; v = (v - d1) >> 8;
        p0.c[i] = (signed char)d0;
        p1.c[i] = (signed char)d1;
        p2.c[i] = (signed char)v;
    }
    *reinterpret_cast<uint2*>(&g_Bq[0][e]) = p0.u;
    *reinterpret_cast<uint2*>(&g_Bq[1][e]) = p1.u;
    *reinterpret_cast<uint2*>(&g_Bq[2][e]) = p2.u;
}

__global__ void __launch_bounds__(256) conv_a(const float* __restrict__ x)
{
    size_t e = ((size_t)blockIdx.x * 256 + threadIdx.x) * 8;
    float4 a = *reinterpret_cast<const float4*>(x + e);
    float4 b = *reinterpret_cast<const float4*>(x + e + 4);
    float w[8] = {a.x, a.y, a.z, a.w, b.x, b.y, b.z, b.w};
    B8 p;
#pragma unroll
    for (int i = 0; i < 8; i++) p.c[i] = (signed char)(w[i] > 0.5f ? 1 : 0);
    *reinterpret_cast<uint2*>(&g_As8[e]) = p.u;
}

// ---------------------------------------------------------------------------
// 16-warp K-split int8 tensor-core GEMM (unchanged from R7).
// ---------------------------------------------------------------------------
#define AST (128 * 144)
#define BST (64 * 144)
#define STB (AST + BST)
#define GRP_SMEM (4 * STB)
#define GSMEM (2 * GRP_SMEM)
#define GITERS 48

__device__ __forceinline__ uint32_t smem_u32(const void* p) {
    uint32_t a;
    asm("{ .reg .u64 t; cvta.to.shared.u64 t, %1; cvt.u32.u64 %0, t; }" : "=r"(a) : "l"(p));
    return a;
}
__device__ __forceinline__ void cpa16(uint32_t dst, const void* src) {
    asm volatile("cp.async.cg.shared.global [%0], [%1], 16;" :: "r"(dst), "l"(src));
}
__device__ __forceinline__ void ldm4(uint32_t& r0, uint32_t& r1, uint32_t& r2, uint32_t& r3,
                                     uint32_t addr) {
    asm volatile("ldmatrix.sync.aligned.m8n8.x4.shared.b16 {%0,%1,%2,%3}, [%4];"
                 : "=r"(r0), "=r"(r1), "=r"(r2), "=r"(r3) : "r"(addr));
}
__device__ __forceinline__ void mma_s8(int* d, const uint32_t* aa, const uint32_t* bb) {
    asm volatile("mma.sync.aligned.m16n8k32.row.col.s32.s8.s8.s32 "
                 "{%0,%1,%2,%3}, {%4,%5,%6,%7}, {%8,%9}, {%0,%1,%2,%3};"
                 : "+r"(d[0]), "+r"(d[1]), "+r"(d[2]), "+r"(d[3])
                 : "r"(aa[0]), "r"(aa[1]), "r"(aa[2]), "r"(aa[3]), "r"(bb[0]), "r"(bb[1]));
}
__device__ __forceinline__ void gbar(int id) {
    asm volatile("bar.sync %0, %1;" :: "r"(id), "r"(256) : "memory");
}

__global__ void __launch_bounds__(512, 1) gemm_i8(const float* __restrict__ bv)
{
    extern __shared__ __align__(128) char dsm[];
    const uint32_t sbase = smem_u32(dsm);

    const int tid512 = threadIdx.x;
    const int g = tid512 >> 8;
    const int tid = tid512 & 255;
    const int wid = tid >> 5;
    const int lane = tid & 31;
    const int nt = blockIdx.x;
    const int mt = blockIdx.y;
    const int wm = wid & 3;
    const int wn = wid >> 2;
    const int gp = lane >> 2;
    const int t4 = lane & 3;
    const uint32_t gbase = sbase + (uint32_t)g * GRP_SMEM;

    int acc[2][4][4];
#pragma unroll
    for (int i = 0; i < 2; i++)
#pragma unroll
        for (int j = 0; j < 4; j++)
#pragma unroll
            for (int q = 0; q < 4; q++) acc[i][j][q] = 0;

    auto load_stage = [&](int s, int it) {
        int plane, chunk;
        if (g == 0) { plane = (it < 32) ? 2 : 0; chunk = (it < 32) ? it : it - 32; }
        else        { plane = (it < 32) ? 1 : 0; chunk = (it < 32) ? it : it - 16; }
        const int k0 = chunk * 128;
        const signed char* Bp = g_Bq[0] + (size_t)plane * ((size_t)DD * DD);
        uint32_t sb = gbase + (uint32_t)s * STB;
#pragma unroll
        for (int q = 0; q < 4; q++) {
            int idx = tid + q * 256;
            int row = idx >> 3, col = idx & 7;
            cpa16(sb + row * 144 + col * 16,
                  g_As8 + (size_t)(mt * 128 + row) * DD + k0 + col * 16);
        }
#pragma unroll
        for (int q = 0; q < 2; q++) {
            int idx = tid + q * 256;
            int row = idx >> 3, col = idx & 7;
            cpa16(sb + AST + row * 144 + col * 16,
                  Bp + (size_t)(nt * 64 + row) * DD + k0 + col * 16);
        }
    };

#pragma unroll
    for (int p = 0; p < 3; p++) {
        load_stage(p, p);
        asm volatile("cp.async.commit_group;");
    }

    const int a_tile = lane >> 3, a_r = lane & 7;
    const int arow_base = wm * 32 + ((a_tile & 1) ? 8 : 0) + a_r;
    const int abyte_base = (a_tile >> 1) ? 16 : 0;
    const int brow_base = wn * 32 + ((a_tile >> 1) ? 8 : 0) + a_r;
    const int bbyte_base = (a_tile & 1) ? 16 : 0;

    for (int i = 0; i < GITERS; i++) {
        asm volatile("cp.async.wait_group 2;");
        gbar(g + 1);
        if (i + 3 < GITERS) load_stage((i + 3) & 3, i + 3);
        asm volatile("cp.async.commit_group;");

        const uint32_t sb = gbase + (uint32_t)(i & 3) * STB;
#pragma unroll
        for (int ks = 0; ks < 4; ks++) {
            uint32_t afr[2][4];
#pragma unroll
            for (int mi = 0; mi < 2; mi++) {
                uint32_t addr = sb + (arow_base + mi * 16) * 144 + abyte_base + ks * 32;
                ldm4(afr[mi][0], afr[mi][1], afr[mi][2], afr[mi][3], addr);
            }
            uint32_t bfr[4][2];
#pragma unroll
            for (int jj = 0; jj < 4; jj += 2) {
                uint32_t addr = sb + AST + (brow_base + jj * 8) * 144 + bbyte_base + ks * 32;
                uint32_t r0, r1, r2, r3;
                ldm4(r0, r1, r2, r3, addr);
                bfr[jj][0] = r0; bfr[jj][1] = r1;
                bfr[jj + 1][0] = r2; bfr[jj + 1][1] = r3;
            }
#pragma unroll
            for (int mi = 0; mi < 2; mi++)
#pragma unroll
                for (int nj = 0; nj < 4; nj++)
                    mma_s8(acc[mi][nj], afr[mi], bfr[nj]);
        }

        if (i == 31) {
            const int sh = (g == 0) ? 16 : 8;
#pragma unroll
            for (int mi = 0; mi < 2; mi++)
#pragma unroll
                for (int nj = 0; nj < 4; nj++)
#pragma unroll
                    for (int q = 0; q < 4; q++) acc[mi][nj][q] <<= sh;
        }
    }

    __syncthreads();
    if (g == 1) {
#pragma unroll
        for (int mi = 0; mi < 2; mi++)
#pragma unroll
            for (int nj = 0; nj < 4; nj++) {
                int row0 = wm * 32 + mi * 16 + gp;
                int col  = wn * 32 + nj * 8 + t4 * 2;
                int* sp = reinterpret_cast<int*>(dsm);
                *reinterpret_cast<int2*>(sp + row0 * 64 + col) =
                    make_int2(acc[mi][nj][0], acc[mi][nj][1]);
                *reinterpret_cast<int2*>(sp + (row0 + 8) * 64 + col) =
                    make_int2(acc[mi][nj][2], acc[mi][nj][3]);
            }
    }
    __syncthreads();
    if (g == 0) {
        const double s = 1.0 / 67108864.0;
        const int* sp = reinterpret_cast<const int*>(dsm);
#pragma unroll
        for (int mi = 0; mi < 2; mi++)
#pragma unroll
            for (int nj = 0; nj < 4; nj++) {
                int lrow = wm * 32 + mi * 16 + gp;
                int col  = wn * 32 + nj * 8 + t4 * 2;
                int2 o0 = *reinterpret_cast<const int2*>(sp + lrow * 64 + col);
                int2 o1 = *reinterpret_cast<const int2*>(sp + (lrow + 8) * 64 + col);
                int row0 = mt * 128 + lrow;
                int gcol = nt * 64 + col;
                float b0 = bv[gcol], b1 = bv[gcol + 1];
                float2 v0, v1;
                v0.x = (float)((double)(acc[mi][nj][0] + o0.x) * s + (double)b0);
                v0.y = (float)((double)(acc[mi][nj][1] + o0.y) * s + (double)b1);
                v1.x = (float)((double)(acc[mi][nj][2] + o1.x) * s + (double)b0);
                v1.y = (float)((double)(acc[mi][nj][3] + o1.y) * s + (double)b1);
                *reinterpret_cast<float2*>(g_grad + (size_t)row0 * DD + gcol) = v0;
                *reinterpret_cast<float2*>(g_grad + (size_t)(row0 + 8) * DD + gcol) = v1;
            }
    }
}

// ---------------------------------------------------------------------------
// lmax_k: per-row max |0.5*grad|
// ---------------------------------------------------------------------------
__global__ void __launch_bounds__(256) lmax_k()
{
    int r = blockIdx.x, tid = threadIdx.x;
    __shared__ float wmax[8];
    float m = 0.f;
#pragma unroll
    for (int i = 0; i < 16; i++)
        m = fmaxf(m, fabsf(0.5f * g_grad[(size_t)r * DD + i * 256 + tid]));
#pragma unroll
    for (int off = 16; off > 0; off >>= 1)
        m = fmaxf(m, __shfl_down_sync(0xffffffffu, m, off));
    if ((tid & 31) == 0) wmax[tid >> 5] = m;
    __syncthreads();
    if (tid == 0) {
        float mm = wmax[0];
        for (int w = 1; w < 8; w++) mm = fmaxf(mm, wmax[w]);
        g_lmax[r] = mm;
    }
}

// ---------------------------------------------------------------------------
// cand_k: per (r,t) candidate shortlist, chain-independent threshold.
// DETERMINISTIC compaction: per-warp counts -> smem scan -> ballot offsets.
// Every byte of g_cand/g_cnt is a pure function of the inputs.
// ---------------------------------------------------------------------------
__global__ void __launch_bounds__(256) cand_k(const float* __restrict__ unif,
                                              const int* __restrict__ radius)
{
    const int t = blockIdx.x, r = blockIdx.y;
    if (t >= radius[r]) return;
    __shared__ float rv[8];
    __shared__ int ri[8];
    __shared__ int wcnt[8];
    const int tid = threadIdx.x, lane = tid & 31, wrp = tid >> 5;

    const float4* up = reinterpret_cast<const float4*>(unif + ((size_t)t * BB + r) * DD);
    float4 U0 = up[tid], U1 = up[256 + tid], U2 = up[512 + tid], U3 = up[768 + tid];
    float uv[16];
    uv[0] = U0.x; uv[1] = U0.y; uv[2] = U0.z; uv[3] = U0.w;
    uv[4] = U1.x; uv[5] = U1.y; uv[6] = U1.z; uv[7] = U1.w;
    uv[8] = U2.x; uv[9] = U2.y; uv[10] = U2.z; uv[11] = U2.w;
    uv[12] = U3.x; uv[13] = U3.y; uv[14] = U3.z; uv[15] = U3.w;

    float um = -1.f; int im = 0;
#pragma unroll
    for (int i = 0; i < 16; i++) {
        int j = (i >> 2) * 1024 + tid * 4 + (i & 3);
        if (uv[i] > um) { um = uv[i]; im = j; }
    }
#pragma unroll
    for (int off = 16; off > 0; off >>= 1) {
        float v2 = __shfl_down_sync(0xffffffffu, um, off);
        int i2 = __shfl_down_sync(0xffffffffu, im, off);
        if (v2 > um || (v2 == um && i2 < im)) { um = v2; im = i2; }
    }
    if (lane == 0) { rv[wrp] = um; ri[wrp] = im; }
    __syncthreads();
    float umax = rv[0]; int imax = ri[0];
#pragma unroll
    for (int w = 1; w < 8; w++) {
        float v2 = rv[w]; int i2 = ri[w];
        if (v2 > umax || (v2 == umax && i2 < imax)) { umax = v2; imax = i2; }
    }

    const float Lm = g_lmax[r];
    const float labs = fabsf(0.5f * g_grad[(size_t)r * DD + imax]);
    const float gm = -logf(-logf(umax));
    const float uth = expf(-expf(-(gm - labs - Lm - 0.05f)));

    // phase 1: per-warp candidate count (deterministic)
    uint32_t masks[16];
    int wtotal = 0;
#pragma unroll
    for (int i = 0; i < 16; i++) {
        masks[i] = __ballot_sync(0xffffffffu, uv[i] >= uth);
        wtotal += __popc(masks[i]);
    }
    if (lane == 0) wcnt[wrp] = wtotal;
    __syncthreads();

    // phase 2: exclusive scan over 8 warps (every thread, redundant)
    int base = 0, total = 0;
#pragma unroll
    for (int w = 0; w < 8; w++) {
        if (w < wrp) base += wcnt[w];
        total += wcnt[w];
    }
    if (tid == 0) g_cnt[r * TT + t] = total;

    // phase 3: deterministic writes at warp-scan offsets
    int2* lst = g_cand + ((size_t)r * TT + t) * CAP;
    const uint32_t lmask = (1u << lane) - 1u;
#pragma unroll
    for (int i = 0; i < 16; i++) {
        uint32_t m = masks[i];
        if (uv[i] >= uth) {
            int pos = base + __popc(m & lmask);
            if (pos < CAP) {
                int j = (i >> 2) * 1024 + tid * 4 + (i & 3);
                float gg = -logf(-logf(uv[i]));
                lst[pos] = make_int2(j, __float_as_int(gg));
            }
        }
        base += __popc(m);
    }
}

// ---------------------------------------------------------------------------
// Sampler: warp-0 barrier-free chain over candidate lists + MH accept.
// ---------------------------------------------------------------------------
#define NT 256
#define PER (DD / NT)

__global__ void __launch_bounds__(NT, 1)
sampler(const float* __restrict__ x, const float* __restrict__ Wm,
        const float* __restrict__ bv, const float* __restrict__ unif,
        const float* __restrict__ u_accept, const int* __restrict__ radius,
        float* __restrict__ out)
{
    __shared__ float lx[DD];
    __shared__ float ly[DD];
    __shared__ signed char ss[DD];
    __shared__ signed char s0[DD];
    __shared__ double rdbl[NT];
    __shared__ int         fidx[TT];
    __shared__ signed char fsb[TT];
    __shared__ int   cidx[TT];
    __shared__ float cfac[TT];
    __shared__ int   nchg;
    __shared__ double sh_sx, sh_sy, sh_sf, sh_sb;
    __shared__ int   sh_acc;

    const int r   = blockIdx.x;
    const int tid = threadIdx.x;
    const int lane = tid & 31;
    const int wrp = tid >> 5;
    const int rad = radius[r];

    // ---- init: lx, signs, score_x ----
    double part = 0.0;
#pragma unroll
    for (int i = 0; i < PER; i++) {
        int j = i * NT + tid;
        float l = 0.5f * g_grad[(size_t)r * DD + j];
        lx[j] = l;
        float xv = x[(size_t)r * DD + j];
        signed char sgn = (xv > 0.5f) ? (signed char)(-1) : (signed char)1;
        ss[j] = sgn; s0[j] = sgn;
        if (sgn < 0) part += (double)(l + 0.5f * bv[j]);
    }
    rdbl[tid] = part; __syncthreads();
    for (int off = NT / 2; off > 0; off >>= 1) {
        if (tid < off) rdbl[tid] += rdbl[tid + off];
        __syncthreads();
    }
    if (tid == 0) sh_sx = rdbl[0];
    __syncthreads();

    // ---- warp-0-only chain over precomputed candidate lists ----
    if (wrp == 0) {
        const float Lmax = g_lmax[r];
        const int2* listbase = g_cand + (size_t)r * TT * CAP;
        for (int t = 0; t < rad; t++) {
            const int cnt = g_cnt[r * TT + t];
            float bv_ = -3.4e38f; int bi = 0x7fffffff;
            if (cnt <= CAP) {
                const int2* lst = listbase + (size_t)t * CAP;
                for (int k = lane; k < cnt; k += 32) {
                    int2 e = lst[k];
                    int j = e.x;
                    float v = (float)ss[j] * lx[j] + __int_as_float(e.y);
                    if (v > bv_ || (v == bv_ && j < bi)) { bv_ = v; bi = j; }
                }
            } else {
                // rare fallback: exact in-warp pruned scan (sign-exact threshold)
                const float* up = unif + ((size_t)t * BB + r) * DD;
                float um = -1.f; int im = 0;
                for (int k = 0; k < DD / 32; k++) {
                    int j = k * 32 + lane;
                    float u = __ldg(up + j);
                    if (u > um) { um = u; im = j; }
                }
#pragma unroll
                for (int off = 16; off > 0; off >>= 1) {
                    float v2 = __shfl_down_sync(0xffffffffu, um, off);
                    int i2 = __shfl_down_sync(0xffffffffu, im, off);
                    if (v2 > um || (v2 == um && i2 < im)) { um = v2; im = i2; }
                }
                um = __shfl_sync(0xffffffffu, um, 0);
                im = __shfl_sync(0xffffffffu, im, 0);
                float slm = (float)ss[im] * lx[im];
                float gm = -logf(-logf(um));
                float uth = expf(-expf(-(gm + slm - Lmax - 0.05f)));
                for (int k = 0; k < DD / 32; k++) {
                    int j = k * 32 + lane;
                    float u = __ldg(up + j);
                    if (u >= uth) {
                        float g = -logf(-logf(u));
                        float v = (float)ss[j] * lx[j] + g;
                        if (v > bv_ || (v == bv_ && j < bi)) { bv_ = v; bi = j; }
                    }
                }
            }
#pragma unroll
            for (int off = 16; off > 0; off >>= 1) {
                float v2 = __shfl_down_sync(0xffffffffu, bv_, off);
                int i2 = __shfl_down_sync(0xffffffffu, bi, off);
                if (v2 > bv_ || (v2 == bv_ && i2 < bi)) { bv_ = v2; bi = i2; }
            }
            bi = __shfl_sync(0xffffffffu, bi, 0);
            if (lane == 0) {
                fidx[t] = bi; fsb[t] = ss[bi];
                ss[bi] = (signed char)(-ss[bi]);
            }
            __syncwarp();
        }
    }
    __syncthreads();

    // ---- net-changed coordinates ----
    if (tid == 0) {
        int n = 0;
        for (int t = 0; t < rad; t++) {
            int i = fidx[t];
            int found = -1;
            for (int k = 0; k < n; k++) if (cidx[k] == i) { found = k; break; }
            if (found >= 0) { cidx[found] = cidx[n - 1]; n--; }
            else cidx[n++] = i;
        }
        nchg = n;
        for (int k = 0; k < n; k++) cfac[k] = -0.5f * (float)ss[cidx[k]];
    }
    __syncthreads();

    // ---- lyr = lx + sum cfac_k * W[i_k] (registers, pipelined loads) ----
    float lyr[PER];
#pragma unroll
    for (int i = 0; i < PER; i++) lyr[i] = lx[i * NT + tid];
    {
        int nc = nchg;
        if (nc > 0) {
            float cur[PER];
            const float* wr = Wm + (size_t)cidx[0] * DD;
#pragma unroll
            for (int i = 0; i < PER; i++) cur[i] = wr[i * NT + tid];
            for (int k = 0; k < nc; k++) {
                float nxt[PER];
                if (k + 1 < nc) {
                    const float* w2 = Wm + (size_t)cidx[k + 1] * DD;
#pragma unroll
                    for (int i = 0; i < PER; i++) nxt[i] = w2[i * NT + tid];
                }
                float f = cfac[k];
#pragma unroll
                for (int i = 0; i < PER; i++) lyr[i] = fmaf(f, cur[i], lyr[i]);
#pragma unroll
                for (int i = 0; i < PER; i++) cur[i] = nxt[i];
            }
        }
    }
#pragma unroll
    for (int i = 0; i < PER; i++) ly[i * NT + tid] = lyr[i];

    // ---- score_y + base lse sums ----
    double psy = 0.0, psf = 0.0, psb = 0.0;
#pragma unroll
    for (int i = 0; i < PER; i++) {
        int j = i * NT + tid;
        float lyj = lyr[i], lxj = lx[j];
        if (ss[j] < 0) psy += (double)(lyj + 0.5f * bv[j]);
        psf += (double)expf((float)s0[j] * lxj);
        psb += (double)expf((float)ss[j] * lyj);
    }
    rdbl[tid] = psy; __syncthreads();
    for (int off = NT / 2; off > 0; off >>= 1) { if (tid < off) rdbl[tid] += rdbl[tid + off]; __syncthreads(); }
    if (tid == 0) sh_sy = rdbl[0];
    __syncthreads();
    rdbl[tid] = psf; __syncthreads();
    for (int off = NT / 2; off > 0; off >>= 1) { if (tid < off) rdbl[tid] += rdbl[tid + off]; __syncthreads(); }
    if (tid == 0) sh_sf = rdbl[0];
    __syncthreads();
    rdbl[tid] = psb; __syncthreads();
    for (int off = NT / 2; off > 0; off >>= 1) { if (tid < off) rdbl[tid] += rdbl[tid + off]; __syncthreads(); }
    if (tid == 0) sh_sb = rdbl[0];
    __syncthreads();

    // ---- serial accept math (incremental lse walks) ----
    if (tid == 0) {
        double S = sh_sf, lf = 0.0;
        for (int t = 0; t < rad; t++) {
            int i = fidx[t]; float sb = (float)fsb[t]; float l = lx[i];
            lf += (double)(sb * l) - log(S);
            S += exp((double)(-sb * l)) - exp((double)(sb * l));
        }
        lf += sh_sx;

        double Sb = sh_sb, lb = 0.0;
        for (int t = rad - 1; t >= 0; t--) {
            int i = fidx[t]; float sb = (float)fsb[t]; float l = ly[i];
            lb += (double)(-sb * l) - log(Sb);
            Sb += exp((double)(sb * l)) - exp((double)(-sb * l));
        }
        lb += sh_sy;

        float ratio = expf((float)(lb - lf));
        sh_acc = (ratio >= u_accept[r]) ? 1 : 0;
    }
    __syncthreads();

    int acc = sh_acc;
#pragma unroll
    for (int i = 0; i < PER; i++) {
        int j = i * NT + tid;
        float yv = (ss[j] < 0) ? 1.f : 0.f;
        float xv = (s0[j] < 0) ? 1.f : 0.f;
        out[(size_t)r * DD + j] = acc ? yv : xv;
    }
}

// ---------------------------------------------------------------------------
extern "C" void kernel_launch(void* const* d_in, const int* in_sizes, int n_in,
                              void* d_out, int out_size)
{
    (void)in_sizes; (void)n_in; (void)out_size;
    const float* x    = (const float*)d_in[0];
    const float* Wm   = (const float*)d_in[1];
    const float* bv   = (const float*)d_in[2];
    const float* unif = (const float*)d_in[3];
    const float* ua   = (const float*)d_in[4];
    const int*   rad  = (const int*)d_in[5];
    float* out = (float*)d_out;

    static int attr_done = 0;
    if (!attr_done) {
        cudaFuncSetAttribute(gemm_i8, cudaFuncAttributeMaxDynamicSharedMemorySize, GSMEM);
        attr_done = 1;
    }

    conv_w<<<8192, 256>>>(Wm);
    conv_a<<<512, 256>>>(x);
    gemm_i8<<<dim3(64, 2), 512, GSMEM>>>(bv);
    lmax_k<<<BB, 256>>>();
    cand_k<<<dim3(TT, BB), 256>>>(unif, rad);
    sampler<<<BB, NT>>>(x, Wm, bv, unif, ua, rad, out);
}